// round 1
// baseline (speedup 1.0000x reference)
#include <cuda_runtime.h>
#include <cstdint>
#include <cfloat>

#define NLEAF   100
#define LSEARCH 10
#define NRE     100
#define MAXB    128
#define MAXN    600000
#define TILE    1024
#define SCORE_CAP (1<<25)   /* 33.5M floats = 128MB scratch for member scores */
#define MAXTILES  1024

/* ------------------------- scratch (__device__ globals; no cudaMalloc) ---- */
__device__ int      d_leaf_cnt[NLEAF];
__device__ int      d_leaf_off[NLEAF + 1];
__device__ int      d_leaf_cur[NLEAF];
__device__ int      d_perm[MAXN];            /* leaf-major candidate ids      */
__device__ unsigned d_qmask[MAXB][4];        /* per-query leaf bitset         */
__device__ int      d_qleaf[MAXB][LSEARCH];  /* per-query top leaves          */
__device__ int      d_leaf_q[NLEAF][MAXB];   /* per-leaf query list           */
__device__ int      d_leaf_nq[NLEAF];
__device__ int      d_leaf_sbase[NLEAF];     /* score-buffer base per leaf    */
__device__ int      d_tile_leaf[MAXTILES];
__device__ int      d_tile_lo[MAXTILES];
__device__ int      d_ntiles;
__device__ float    d_lut[MAXB * 1024];      /* per-query PQ lookup tables    */
__device__ float    d_sbuf[SCORE_CAP];       /* member ah-scores              */
__device__ int      d_sel[MAXB * NRE];       /* top-100 candidate ids, sorted */

__device__ __forceinline__ unsigned fkey(float f) {
    unsigned u = __float_as_uint(f);
    return (u & 0x80000000u) ? ~u : (u | 0x80000000u);
}

/* ------------------------- K0: zero counters ----------------------------- */
__global__ void k_zero(int B) {
    int t = threadIdx.x + blockIdx.x * blockDim.x;
    if (t < NLEAF) { d_leaf_cnt[t] = 0; d_leaf_cur[t] = 0; }
    if (t < B * 4) ((unsigned*)d_qmask)[t] = 0u;
}

/* ------------------------- K1: center scores + top-10 leaves ------------- */
__global__ void k_centers(const float* __restrict__ queries,
                          const float* __restrict__ centers) {
    int q = blockIdx.x;
    int tid = threadIdx.x;
    __shared__ float qs[128];
    __shared__ float sc[128];
    qs[tid] = queries[q * 128 + tid];
    __syncthreads();
    float acc = -FLT_MAX;
    if (tid < NLEAF) {
        acc = 0.f;
        #pragma unroll 8
        for (int d = 0; d < 128; d++) acc += qs[d] * centers[tid * 128 + d];
    }
    sc[tid] = acc;
    __syncthreads();
    if (tid < 32) {
        for (int it = 0; it < LSEARCH; it++) {
            float bv = -FLT_MAX; int bi = 0x7fffffff;
            for (int t = tid; t < NLEAF; t += 32) {
                float v = sc[t];
                if (v > bv || (v == bv && t < bi)) { bv = v; bi = t; }
            }
            #pragma unroll
            for (int o = 16; o; o >>= 1) {
                float ov = __shfl_xor_sync(0xffffffffu, bv, o);
                int   oi = __shfl_xor_sync(0xffffffffu, bi, o);
                if (ov > bv || (ov == bv && oi < bi)) { bv = ov; bi = oi; }
            }
            if (tid == 0) {
                d_qleaf[q][it] = bi;
                d_qmask[q][bi >> 5] |= (1u << (bi & 31));
                sc[bi] = -FLT_MAX;
            }
            __syncwarp();
        }
    }
}

/* ------------------------- K1b: invert to per-leaf query lists ----------- */
__global__ void k_leaflists(int B) {
    int l = threadIdx.x;
    if (l >= NLEAF) return;
    int nq = 0;
    for (int q = 0; q < B; q++)
        if (d_qmask[q][l >> 5] & (1u << (l & 31))) d_leaf_q[l][nq++] = q;
    d_leaf_nq[l] = nq;
}

/* ------------------------- K1c: per-query PQ LUTs (warp-shfl layout) ----- */
/* d_lut[q*1024 + jj*32 + lane] = LUT[2jj + (lane>=16)][lane&15]             */
__global__ void k_lut(const float* __restrict__ queries,
                      const float* __restrict__ cb) {
    int q = blockIdx.x;
    int e = threadIdx.x;           /* 1024 threads */
    int jj = e >> 5, lane = e & 31;
    int j = 2 * jj + (lane >= 16 ? 1 : 0);
    int c = lane & 15;
    float v = queries[q * 128 + 2 * j]     * cb[(j * 16 + c) * 2 + 0]
            + queries[q * 128 + 2 * j + 1] * cb[(j * 16 + c) * 2 + 1];
    d_lut[q * 1024 + e] = v;
}

/* ------------------------- K2: leaf histogram ---------------------------- */
__global__ void k_hist(const int* __restrict__ cl, int N) {
    for (int n = blockIdx.x * blockDim.x + threadIdx.x; n < N;
         n += gridDim.x * blockDim.x)
        atomicAdd(&d_leaf_cnt[cl[n]], 1);
}

/* ------------------------- K2b: prefix sums + tile table (serial) -------- */
__global__ void k_meta() {
    if (threadIdx.x != 0 || blockIdx.x != 0) return;
    int off = 0;
    for (int l = 0; l < NLEAF; l++) { d_leaf_off[l] = off; off += d_leaf_cnt[l]; }
    d_leaf_off[NLEAF] = off;
    long long sb = 0;
    for (int l = 0; l < NLEAF; l++) {
        d_leaf_sbase[l] = (int)sb;
        sb += (long long)d_leaf_nq[l] * d_leaf_cnt[l];
        if (sb > SCORE_CAP) sb = SCORE_CAP;    /* pathological-only clamp */
    }
    int nt = 0;
    for (int l = 0; l < NLEAF; l++) {
        if (d_leaf_nq[l] == 0) continue;
        for (int lo = 0; lo < d_leaf_cnt[l] && nt < MAXTILES; lo += TILE) {
            d_tile_leaf[nt] = l; d_tile_lo[nt] = lo; nt++;
        }
    }
    d_ntiles = nt;
}

/* ------------------------- K2c: scatter to leaf-major order -------------- */
__global__ void k_scatter(const int* __restrict__ cl, int N) {
    for (int n = blockIdx.x * blockDim.x + threadIdx.x; n < N;
         n += gridDim.x * blockDim.x) {
        int l = cl[n];
        int p = atomicAdd(&d_leaf_cur[l], 1);
        d_perm[d_leaf_off[l] + p] = n;
    }
}

/* ------------------------- K3: PQ scoring (shfl-LUT) --------------------- */
__global__ void __launch_bounds__(256) k_score(const int* __restrict__ codes) {
    int bx = blockIdx.x;
    if (bx >= d_ntiles) return;
    int leaf = d_tile_leaf[bx];
    int lo   = d_tile_lo[bx];
    int cnt  = d_leaf_cnt[leaf];
    int count = min(TILE, cnt - lo);
    int off  = d_leaf_off[leaf];

    __shared__ unsigned sh[TILE * 9];   /* 4-bit packed codes, stride 9 words */
    int tid = threadIdx.x;
    for (int i = tid; i < count; i += blockDim.x) {
        int n = d_perm[off + lo + i];
        const uint4* cp = (const uint4*)(codes + (size_t)n * 64);
        #pragma unroll
        for (int w = 0; w < 8; w++) {
            uint4 a = cp[2 * w], b = cp[2 * w + 1];
            unsigned word = (a.x & 15)        | ((a.y & 15) << 4)
                          | ((a.z & 15) << 8) | ((a.w & 15) << 12)
                          | ((b.x & 15) << 16)| ((b.y & 15) << 20)
                          | ((b.z & 15) << 24)| ((b.w & 15) << 28);
            sh[i * 9 + w] = word;
        }
    }
    __syncthreads();

    int warp = tid >> 5, lane = tid & 31, nw = blockDim.x >> 5;
    int nq = d_leaf_nq[leaf];
    int sbase = d_leaf_sbase[leaf];

    for (int qi = warp; qi < nq; qi += nw) {
        int q = d_leaf_q[leaf][qi];
        float lut[32];
        const float* lp = d_lut + q * 1024 + lane;
        #pragma unroll
        for (int jj = 0; jj < 32; jj++) lut[jj] = lp[jj * 32];

        int wbase = sbase + qi * cnt + lo;
        for (int c0 = 0; c0 < count; c0 += 32) {
            int c  = c0 + lane;
            int cc = min(c, count - 1);
            unsigned cw[8];
            #pragma unroll
            for (int w = 0; w < 8; w++) cw[w] = sh[cc * 9 + w];
            float a0 = 0.f, a1 = 0.f;
            #pragma unroll
            for (int w = 0; w < 8; w++) {
                #pragma unroll
                for (int t = 0; t < 4; t++) {
                    int n0 = (cw[w] >> (8 * t)) & 15;
                    int n1 = (cw[w] >> (8 * t + 4)) & 15;
                    a0 += __shfl_sync(0xffffffffu, lut[4 * w + t], n0);
                    a1 += __shfl_sync(0xffffffffu, lut[4 * w + t], n1 + 16);
                }
            }
            if (c < count) {
                int idx = wbase + c;
                if (idx < SCORE_CAP) d_sbuf[idx] = a0 + a1;
            }
        }
    }
}

/* ------------------------- K4: exact top-100 per query (radix select) ---- */
__global__ void __launch_bounds__(512) k_select(int B) {
    int q = blockIdx.x;
    if (q >= B) return;
    int tid = threadIdx.x;

    __shared__ int seg_base[LSEARCH], seg_len[LSEARCH], seg_poff[LSEARCH];
    __shared__ int hist[256];
    __shared__ unsigned long long keys[128];
    __shared__ int tieids[1024];
    __shared__ int sh_bin, sh_above, sh_na, sh_nt, sh_tot;

    if (tid < LSEARCH) {
        int l = d_qleaf[q][tid];
        int nq = d_leaf_nq[l];
        int slot = 0;
        for (int i = 0; i < nq; i++) if (d_leaf_q[l][i] == q) { slot = i; break; }
        seg_base[tid] = d_leaf_sbase[l] + slot * d_leaf_cnt[l];
        seg_len[tid]  = d_leaf_cnt[l];
        seg_poff[tid] = d_leaf_off[l];
    }
    if (tid == 0) { sh_na = 0; sh_nt = 0; }
    __syncthreads();
    if (tid == 0) {
        int t = 0;
        for (int s = 0; s < LSEARCH; s++) t += seg_len[s];
        sh_tot = t;
    }
    __syncthreads();
    int tot = sh_tot;

    unsigned prefix = 0;
    int need = NRE;
    unsigned T;
    if (tot <= NRE) {
        T = 0u; need = 0;   /* everything qualifies as "above" */
    } else {
        for (int pass = 3; pass >= 0; pass--) {
            int shift = pass * 8;
            for (int i = tid; i < 256; i += blockDim.x) hist[i] = 0;
            __syncthreads();
            for (int s = 0; s < LSEARCH; s++) {
                int len = seg_len[s], base = seg_base[s];
                for (int i = tid; i < len; i += blockDim.x) {
                    unsigned m = fkey(d_sbuf[base + i]);
                    bool match = (pass == 3) || ((m >> (shift + 8)) == prefix);
                    if (match) atomicAdd(&hist[(m >> shift) & 255], 1);
                }
            }
            __syncthreads();
            if (tid == 0) {
                int cum = 0, found = 0;
                for (int b = 255; b >= 0; b--) {
                    int c = hist[b];
                    if (cum + c >= need) { sh_bin = b; sh_above = cum; found = 1; break; }
                    cum += c;
                }
                if (!found) { sh_bin = 0; sh_above = cum; }
            }
            __syncthreads();
            int b = sh_bin, ab = sh_above;
            __syncthreads();
            need -= ab;
            prefix = (prefix << 8) | (unsigned)b;
        }
        T = prefix;
    }

    /* compaction: strictly-above + ties */
    for (int s = 0; s < LSEARCH; s++) {
        int len = seg_len[s], base = seg_base[s], poff = seg_poff[s];
        for (int i = tid; i < len; i += blockDim.x) {
            unsigned m = fkey(d_sbuf[base + i]);
            if (m > T) {
                int p = atomicAdd(&sh_na, 1);
                if (p < NRE) {
                    int id = d_perm[poff + i];
                    keys[p] = ((unsigned long long)m << 32) | (unsigned)(~(unsigned)id);
                }
            } else if (m == T && need > 0) {
                int p = atomicAdd(&sh_nt, 1);
                if (p < 1024) tieids[p] = d_perm[poff + i];
            }
        }
    }
    __syncthreads();
    int na = min(sh_na, NRE);
    int nt = min(sh_nt, 1024);
    int take = min(need, nt);
    if (tid == 0) {
        /* partial selection: smallest `take` candidate ids among ties */
        for (int r = 0; r < take; r++) {
            int mi = r;
            for (int i = r + 1; i < nt; i++) if (tieids[i] < tieids[mi]) mi = i;
            int tmp = tieids[r]; tieids[r] = tieids[mi]; tieids[mi] = tmp;
            if (na + r < 128)
                keys[na + r] = ((unsigned long long)T << 32)
                             | (unsigned)(~(unsigned)tieids[r]);
        }
    }
    __syncthreads();
    int total = min(na + take, 128);
    for (int i = tid; i < 128; i += blockDim.x)
        if (i >= total) keys[i] = 0ull;
    __syncthreads();

    /* bitonic sort, 128 keys, descending (score desc, id asc) */
    for (int ksz = 2; ksz <= 128; ksz <<= 1) {
        for (int j = ksz >> 1; j > 0; j >>= 1) {
            __syncthreads();
            if (tid < 64) {
                int i = ((tid / j) * (j << 1)) + (tid % j);
                int p = i + j;
                bool dsc = ((i & ksz) == 0);
                unsigned long long a = keys[i], b = keys[p];
                if ((a < b) == dsc) { keys[i] = b; keys[p] = a; }
            }
        }
    }
    __syncthreads();
    for (int r = tid; r < NRE; r += blockDim.x) {
        unsigned long long kk = keys[r];
        d_sel[q * NRE + r] = (kk == 0ull) ? -1
                           : (int)(~(unsigned)(kk & 0xffffffffull));
    }
}

/* ------------------------- K5: exact rerank + top-k + output ------------- */
__global__ void k_rerank(const float* __restrict__ queries,
                         const float* __restrict__ cands,
                         const int*   __restrict__ identifiers,
                         float* __restrict__ out,
                         int B, int N, int kk) {
    int q = blockIdx.x;
    if (q >= B) return;
    int tid = threadIdx.x, warp = tid >> 5, lane = tid & 31;
    __shared__ float qs[128];
    __shared__ float ex[NRE];
    qs[tid] = queries[q * 128 + tid];
    __syncthreads();

    for (int r = warp; r < NRE; r += 4) {
        int id = d_sel[q * NRE + r];
        float acc = 0.f;
        bool ok = ((unsigned)id < (unsigned)N);
        if (ok) {
            const float* c = cands + (size_t)id * 128;
            acc = qs[lane] * c[lane] + qs[lane + 32] * c[lane + 32]
                + qs[lane + 64] * c[lane + 64] + qs[lane + 96] * c[lane + 96];
        }
        #pragma unroll
        for (int o = 16; o; o >>= 1) acc += __shfl_xor_sync(0xffffffffu, acc, o);
        if (lane == 0) ex[r] = ok ? acc : -1e30f;
    }
    __syncthreads();

    if (warp == 0) {
        for (int it = 0; it < kk; it++) {
            float bv = -FLT_MAX; int bi = NRE;
            for (int r = lane; r < NRE; r += 32) {
                float v = ex[r];
                if (v > bv || (v == bv && r < bi)) { bv = v; bi = r; }
            }
            #pragma unroll
            for (int o = 16; o; o >>= 1) {
                float ov = __shfl_xor_sync(0xffffffffu, bv, o);
                int   oi = __shfl_xor_sync(0xffffffffu, bi, o);
                if (ov > bv || (ov == bv && oi < bi)) { bv = ov; bi = oi; }
            }
            if (lane == 0) {
                int cid = (bi < NRE) ? d_sel[q * NRE + bi] : -1;
                out[q * kk + it] = bv;
                float idv = 0.f;
                if ((unsigned)cid < (unsigned)N) idv = (float)identifiers[cid];
                out[(size_t)B * kk + q * kk + it] = idv;
                if (bi < NRE) ex[bi] = -FLT_MAX;
            }
            __syncwarp();
        }
    }
}

/* ------------------------- host launcher --------------------------------- */
extern "C" void kernel_launch(void* const* d_in, const int* in_sizes, int n_in,
                              void* d_out, int out_size) {
    const float* queries    = (const float*)d_in[0];
    const float* candidates = (const float*)d_in[1];
    const float* centers    = (const float*)d_in[2];
    const float* codebooks  = (const float*)d_in[3];
    const int*   codes      = (const int*)d_in[4];
    const int*   cand_leaf  = (const int*)d_in[5];
    const int*   identifiers= (const int*)d_in[6];

    int B = in_sizes[0] / 128;
    int N = in_sizes[1] / 128;
    if (B > MAXB) B = MAXB;
    int kk = (B > 0) ? out_size / (2 * B) : 10;
    if (kk <= 0 || kk > NRE) kk = 10;

    float* out = (float*)d_out;

    k_zero<<<2, 256>>>(B);
    k_centers<<<B, 128>>>(queries, centers);
    k_leaflists<<<1, 128>>>(B);
    k_lut<<<B, 1024>>>(queries, codebooks);
    k_hist<<<256, 256>>>(cand_leaf, N);
    k_meta<<<1, 32>>>();
    k_scatter<<<256, 256>>>(cand_leaf, N);

    int maxTiles = (N + TILE - 1) / TILE + NLEAF;
    if (maxTiles > MAXTILES) maxTiles = MAXTILES;
    k_score<<<maxTiles, 256>>>(codes);

    k_select<<<B, 512>>>(B);
    k_rerank<<<B, 128>>>(queries, candidates, identifiers, out, B, N, kk);
}

// round 2
// speedup vs baseline: 1.0145x; 1.0145x over previous
#include <cuda_runtime.h>
#include <cstdint>
#include <cfloat>

#define NLEAF   100
#define LSEARCH 10
#define NRE     100
#define MAXB    128
#define MAXN    600000
#define TILE    1024
#define SCORE_CAP (1<<25)
#define MAXTILES  1024
#define SELCAP  4096            /* survivor capacity in k_select */

/* ------------------------- scratch (__device__ globals) ------------------ */
__device__ int      d_leaf_cnt[NLEAF];
__device__ int      d_leaf_off[NLEAF + 1];
__device__ int      d_leaf_cur[NLEAF];
__device__ int      d_perm[MAXN];
__device__ int      d_qleaf[MAXB][LSEARCH];
__device__ int      d_leaf_q[NLEAF][MAXB];
__device__ int      d_leaf_nq[NLEAF];
__device__ int      d_leaf_sbase[NLEAF];
__device__ int      d_tile_leaf[MAXTILES];
__device__ int      d_tile_lo[MAXTILES];
__device__ int      d_ntiles;
__device__ float    d_lut[MAXB * 1024];
__device__ float    d_sbuf[SCORE_CAP];
__device__ int      d_sel[MAXB * NRE];

__device__ __forceinline__ unsigned fkey(float f) {
    unsigned u = __float_as_uint(f);
    return (u & 0x80000000u) ? ~u : (u | 0x80000000u);
}

/* ---- K1: zero counters + center scores + top-10 leaves + PQ LUT --------- */
__global__ void k_centers(const float* __restrict__ queries,
                          const float* __restrict__ centers,
                          const float* __restrict__ cb) {
    int q = blockIdx.x;
    int tid = threadIdx.x;
    __shared__ float qs[128];
    __shared__ float sc[128];

    if (q == 0 && tid < NLEAF) { d_leaf_cnt[tid] = 0; d_leaf_cur[tid] = 0; }

    qs[tid] = queries[q * 128 + tid];
    __syncthreads();
    float acc = -FLT_MAX;
    if (tid < NLEAF) {
        acc = 0.f;
        #pragma unroll 8
        for (int d = 0; d < 128; d++) acc += qs[d] * centers[tid * 128 + d];
    }
    sc[tid] = acc;
    __syncthreads();
    if (tid < 32) {
        for (int it = 0; it < LSEARCH; it++) {
            float bv = -FLT_MAX; int bi = 0x7fffffff;
            for (int t = tid; t < NLEAF; t += 32) {
                float v = sc[t];
                if (v > bv || (v == bv && t < bi)) { bv = v; bi = t; }
            }
            #pragma unroll
            for (int o = 16; o; o >>= 1) {
                float ov = __shfl_xor_sync(0xffffffffu, bv, o);
                int   oi = __shfl_xor_sync(0xffffffffu, bi, o);
                if (ov > bv || (ov == bv && oi < bi)) { bv = ov; bi = oi; }
            }
            if (tid == 0) { d_qleaf[q][it] = bi; sc[bi] = -FLT_MAX; }
            __syncwarp();
        }
    }
    __syncthreads();
    /* PQ LUT: d_lut[q*1024 + jj*32 + lane] = LUT[2jj+(lane>=16)][lane&15] */
    #pragma unroll
    for (int r = 0; r < 8; r++) {
        int e = tid + 128 * r;
        int lane = e & 31;
        int j = 2 * (e >> 5) + (lane >= 16 ? 1 : 0);
        int c = lane & 15;
        d_lut[q * 1024 + e] = qs[2 * j]     * cb[(j * 16 + c) * 2 + 0]
                            + qs[2 * j + 1] * cb[(j * 16 + c) * 2 + 1];
    }
}

/* ---- K2: leaf histogram -------------------------------------------------- */
__global__ void k_hist(const int* __restrict__ cl, int N) {
    for (int n = blockIdx.x * blockDim.x + threadIdx.x; n < N;
         n += gridDim.x * blockDim.x)
        atomicAdd(&d_leaf_cnt[cl[n]], 1);
}

/* ---- K3: invert to per-leaf query lists ---------------------------------- */
__global__ void k_leaflists(int B) {
    int l = threadIdx.x;
    if (l >= NLEAF) return;
    int nq = 0;
    for (int q = 0; q < B; q++) {
        bool mem = false;
        #pragma unroll
        for (int t = 0; t < LSEARCH; t++) if (d_qleaf[q][t] == l) mem = true;
        if (mem) d_leaf_q[l][nq++] = q;
    }
    d_leaf_nq[l] = nq;
}

/* ---- K4: prefix sums + tile table ---------------------------------------- */
__global__ void k_meta() {
    if (threadIdx.x != 0 || blockIdx.x != 0) return;
    int off = 0;
    for (int l = 0; l < NLEAF; l++) { d_leaf_off[l] = off; off += d_leaf_cnt[l]; }
    d_leaf_off[NLEAF] = off;
    long long sb = 0;
    for (int l = 0; l < NLEAF; l++) {
        d_leaf_sbase[l] = (int)sb;
        sb += (long long)d_leaf_nq[l] * d_leaf_cnt[l];
        if (sb > SCORE_CAP) sb = SCORE_CAP;
    }
    int nt = 0;
    for (int l = 0; l < NLEAF; l++) {
        if (d_leaf_nq[l] == 0) continue;
        for (int lo = 0; lo < d_leaf_cnt[l] && nt < MAXTILES; lo += TILE) {
            d_tile_leaf[nt] = l; d_tile_lo[nt] = lo; nt++;
        }
    }
    d_ntiles = nt;
}

/* ---- K5: scatter to leaf-major order ------------------------------------- */
__global__ void k_scatter(const int* __restrict__ cl, int N) {
    for (int n = blockIdx.x * blockDim.x + threadIdx.x; n < N;
         n += gridDim.x * blockDim.x) {
        int l = cl[n];
        int p = atomicAdd(&d_leaf_cur[l], 1);
        d_perm[d_leaf_off[l] + p] = n;
    }
}

/* ---- K6: PQ scoring (warp-shuffle LUT) ----------------------------------- */
__global__ void __launch_bounds__(256) k_score(const int* __restrict__ codes) {
    int bx = blockIdx.x;
    if (bx >= d_ntiles) return;
    int leaf = d_tile_leaf[bx];
    int lo   = d_tile_lo[bx];
    int cnt  = d_leaf_cnt[leaf];
    int count = min(TILE, cnt - lo);
    int off  = d_leaf_off[leaf];

    __shared__ unsigned sh[TILE * 9];
    int tid = threadIdx.x;
    for (int i = tid; i < count; i += blockDim.x) {
        int n = d_perm[off + lo + i];
        const uint4* cp = (const uint4*)(codes + (size_t)n * 64);
        #pragma unroll
        for (int w = 0; w < 8; w++) {
            uint4 a = cp[2 * w], b = cp[2 * w + 1];
            unsigned word = (a.x & 15)        | ((a.y & 15) << 4)
                          | ((a.z & 15) << 8) | ((a.w & 15) << 12)
                          | ((b.x & 15) << 16)| ((b.y & 15) << 20)
                          | ((b.z & 15) << 24)| ((b.w & 15) << 28);
            sh[i * 9 + w] = word;
        }
    }
    __syncthreads();

    int warp = tid >> 5, lane = tid & 31, nw = blockDim.x >> 5;
    int nq = d_leaf_nq[leaf];
    int sbase = d_leaf_sbase[leaf];

    for (int qi = warp; qi < nq; qi += nw) {
        int q = d_leaf_q[leaf][qi];
        float lut[32];
        const float* lp = d_lut + q * 1024 + lane;
        #pragma unroll
        for (int jj = 0; jj < 32; jj++) lut[jj] = lp[jj * 32];

        int wbase = sbase + qi * cnt + lo;
        for (int c0 = 0; c0 < count; c0 += 32) {
            int c  = c0 + lane;
            int cc = min(c, count - 1);
            unsigned cw[8];
            #pragma unroll
            for (int w = 0; w < 8; w++) cw[w] = sh[cc * 9 + w];
            float a0 = 0.f, a1 = 0.f;
            #pragma unroll
            for (int w = 0; w < 8; w++) {
                #pragma unroll
                for (int t = 0; t < 4; t++) {
                    int n0 = (cw[w] >> (8 * t)) & 15;
                    int n1 = (cw[w] >> (8 * t + 4)) & 15;
                    a0 += __shfl_sync(0xffffffffu, lut[4 * w + t], n0);
                    a1 += __shfl_sync(0xffffffffu, lut[4 * w + t], n1 + 16);
                }
            }
            if (c < count) {
                int idx = wbase + c;
                if (idx < SCORE_CAP) d_sbuf[idx] = a0 + a1;
            }
        }
    }
}

/* ---- K7: exact top-100 per query: sampled threshold + compact + sort ---- */
__global__ void __launch_bounds__(512) k_select(int B) {
    int q = blockIdx.x;
    if (q >= B) return;
    int tid = threadIdx.x;
    int lane = tid & 31;

    __shared__ unsigned long long keys[SELCAP];   /* 32KB; hist aliases front */
    int* hist = (int*)keys;                       /* 4096 bins = 16KB        */
    __shared__ int csum[512];
    __shared__ int seg_base[LSEARCH], seg_len[LSEARCH], seg_poff[LSEARCH];
    __shared__ int s_bin, s_cnt, s_tot;

    if (tid < LSEARCH) {
        int l = d_qleaf[q][tid];
        int nq = d_leaf_nq[l];
        int slot = 0;
        for (int i = 0; i < nq; i++) if (d_leaf_q[l][i] == q) { slot = i; break; }
        seg_base[tid] = d_leaf_sbase[l] + slot * d_leaf_cnt[l];
        seg_len[tid]  = d_leaf_cnt[l];
        seg_poff[tid] = d_leaf_off[l];
    }
    __syncthreads();
    if (tid == 0) {
        int t = 0;
        for (int s = 0; s < LSEARCH; s++) t += seg_len[s];
        s_tot = t;
    }
    __syncthreads();
    int tot = s_tot;

    unsigned T = 0u;
    int attempt = 0;
    int m = 0;

    for (;;) {
        if (tot > SELCAP) {
            /* histogram pass: attempt 0 = every 16th element; attempt 1 = all */
            for (int i = tid; i < 4096; i += 512) hist[i] = 0;
            if (tid == 0) s_bin = 0;
            __syncthreads();
            if (attempt == 0) {
                for (int s = 0; s < LSEARCH; s++) {
                    int len = seg_len[s], base = seg_base[s];
                    for (int i = tid; i * 16 < len; i += 512) {
                        unsigned mm = fkey(d_sbuf[base + i * 16]);
                        atomicAdd(&hist[mm >> 20], 1);
                    }
                }
            } else {
                for (int s = 0; s < LSEARCH; s++) {
                    int len = seg_len[s], base = seg_base[s];
                    for (int i = tid; i < len; i += 512) {
                        unsigned mm = fkey(d_sbuf[base + i]);
                        atomicAdd(&hist[mm >> 20], 1);
                    }
                }
            }
            __syncthreads();
            /* chunk sums (8 bins/thread), then suffix-scan over 512 chunks */
            {
                int ssum = 0;
                #pragma unroll
                for (int b = 0; b < 8; b++) ssum += hist[tid * 8 + b];
                csum[tid] = ssum;
            }
            __syncthreads();
            for (int offst = 1; offst < 512; offst <<= 1) {
                int add = (tid + offst < 512) ? csum[tid + offst] : 0;
                __syncthreads();
                csum[tid] += add;
                __syncthreads();
            }
            /* locate crossing bin: cum(>=b) first reaches >= NRE */
            {
                int running = (tid == 511) ? 0 : csum[tid + 1];
                for (int b = tid * 8 + 7; b >= tid * 8; b--) {
                    int h = hist[b];
                    if (running < NRE && running + h >= NRE) s_bin = b;
                    running += h;
                }
            }
            __syncthreads();
            T = (unsigned)s_bin << 20;
        } else {
            T = 0u;   /* everything fits: compact all */
        }

        /* compaction with warp-aggregated counter */
        if (tid == 0) s_cnt = 0;
        __syncthreads();
        for (int s = 0; s < LSEARCH; s++) {
            int len = seg_len[s], base = seg_base[s], poff = seg_poff[s];
            for (int i0 = 0; i0 < len; i0 += 512) {
                int i = i0 + tid;
                unsigned mm = 0u;
                bool pred = false;
                if (i < len) {
                    mm = fkey(d_sbuf[base + i]);
                    pred = (mm >= T);
                }
                unsigned bal = __ballot_sync(0xffffffffu, pred);
                int basep = 0;
                if (lane == 0 && bal) basep = atomicAdd(&s_cnt, __popc(bal));
                basep = __shfl_sync(0xffffffffu, basep, 0);
                if (pred) {
                    int pos = basep + __popc(bal & ((1u << lane) - 1u));
                    if (pos < SELCAP) {
                        int id = d_perm[poff + i];
                        keys[pos] = ((unsigned long long)mm << 32)
                                  | (unsigned)(~(unsigned)id);
                    }
                }
            }
        }
        __syncthreads();
        m = s_cnt;
        if (m <= SELCAP || attempt >= 1 || tot <= SELCAP) break;
        attempt = 1;   /* sampled threshold overflowed: redo with exact hist */
        __syncthreads();
    }

    int m_eff = min(m, SELCAP);
    int NS = 128;
    while (NS < m_eff) NS <<= 1;     /* NS <= SELCAP */
    for (int i = tid; i < NS; i += 512)
        if (i >= m_eff) keys[i] = 0ull;
    __syncthreads();

    /* bitonic sort descending by (score, then id asc via ~id) */
    for (int k2 = 2; k2 <= NS; k2 <<= 1) {
        for (int j = k2 >> 1; j > 0; j >>= 1) {
            for (int idx = tid; idx < (NS >> 1); idx += 512) {
                int i = ((idx / j) * (j << 1)) + (idx % j);
                int p = i + j;
                bool dsc = ((i & k2) == 0);
                unsigned long long a = keys[i], b = keys[p];
                if ((a < b) == dsc) { keys[i] = b; keys[p] = a; }
            }
            __syncthreads();
        }
    }

    for (int r = tid; r < NRE; r += 512) {
        unsigned long long kk = (r < m_eff) ? keys[r] : 0ull;
        d_sel[q * NRE + r] = (kk == 0ull) ? -1
                           : (int)(~(unsigned)(kk & 0xffffffffull));
    }
}

/* ---- K8: exact rerank + final top-k + output ----------------------------- */
__global__ void k_rerank(const float* __restrict__ queries,
                         const float* __restrict__ cands,
                         const int*   __restrict__ identifiers,
                         float* __restrict__ out,
                         int B, int N, int kk) {
    int q = blockIdx.x;
    if (q >= B) return;
    int tid = threadIdx.x, warp = tid >> 5, lane = tid & 31;
    __shared__ float qs[128];
    __shared__ float ex[NRE];
    qs[tid] = queries[q * 128 + tid];
    __syncthreads();

    for (int r = warp; r < NRE; r += 4) {
        int id = d_sel[q * NRE + r];
        float acc = 0.f;
        bool ok = ((unsigned)id < (unsigned)N);
        if (ok) {
            const float* c = cands + (size_t)id * 128;
            acc = qs[lane] * c[lane] + qs[lane + 32] * c[lane + 32]
                + qs[lane + 64] * c[lane + 64] + qs[lane + 96] * c[lane + 96];
        }
        #pragma unroll
        for (int o = 16; o; o >>= 1) acc += __shfl_xor_sync(0xffffffffu, acc, o);
        if (lane == 0) ex[r] = ok ? acc : -1e30f;
    }
    __syncthreads();

    if (warp == 0) {
        for (int it = 0; it < kk; it++) {
            float bv = -FLT_MAX; int bi = NRE;
            for (int r = lane; r < NRE; r += 32) {
                float v = ex[r];
                if (v > bv || (v == bv && r < bi)) { bv = v; bi = r; }
            }
            #pragma unroll
            for (int o = 16; o; o >>= 1) {
                float ov = __shfl_xor_sync(0xffffffffu, bv, o);
                int   oi = __shfl_xor_sync(0xffffffffu, bi, o);
                if (ov > bv || (ov == bv && oi < bi)) { bv = ov; bi = oi; }
            }
            if (lane == 0) {
                int cid = (bi < NRE) ? d_sel[q * NRE + bi] : -1;
                out[q * kk + it] = bv;
                float idv = 0.f;
                if ((unsigned)cid < (unsigned)N) idv = (float)identifiers[cid];
                out[(size_t)B * kk + q * kk + it] = idv;
                if (bi < NRE) ex[bi] = -FLT_MAX;
            }
            __syncwarp();
        }
    }
}

/* ---- host launcher ------------------------------------------------------- */
extern "C" void kernel_launch(void* const* d_in, const int* in_sizes, int n_in,
                              void* d_out, int out_size) {
    const float* queries    = (const float*)d_in[0];
    const float* candidates = (const float*)d_in[1];
    const float* centers    = (const float*)d_in[2];
    const float* codebooks  = (const float*)d_in[3];
    const int*   codes      = (const int*)d_in[4];
    const int*   cand_leaf  = (const int*)d_in[5];
    const int*   identifiers= (const int*)d_in[6];

    int B = in_sizes[0] / 128;
    int N = in_sizes[1] / 128;
    if (B > MAXB) B = MAXB;
    int kk = (B > 0) ? out_size / (2 * B) : 10;
    if (kk <= 0 || kk > NRE) kk = 10;

    float* out = (float*)d_out;

    k_centers<<<B, 128>>>(queries, centers, codebooks);   /* 1 */
    k_hist<<<256, 256>>>(cand_leaf, N);                   /* 2 */
    k_leaflists<<<1, 128>>>(B);                           /* 3 */
    k_meta<<<1, 32>>>();                                  /* 4 */
    k_scatter<<<256, 256>>>(cand_leaf, N);                /* 5 */

    int maxTiles = (N + TILE - 1) / TILE + NLEAF;
    if (maxTiles > MAXTILES) maxTiles = MAXTILES;
    k_score<<<maxTiles, 256>>>(codes);                    /* 6 <- profiled */

    k_select<<<B, 512>>>(B);                              /* 7 */
    k_rerank<<<B, 128>>>(queries, candidates, identifiers, out, B, N, kk); /* 8 */
}

// round 5
// speedup vs baseline: 1.9212x; 1.8938x over previous
#include <cuda_runtime.h>
#include <cstdint>
#include <cfloat>

#define NLEAF   100
#define LSEARCH 10
#define NRE     100
#define MAXB    128
#define MAXN    600000
#define TILE    1024
#define SCORE_CAP (1<<25)
#define MAXTILES  1024
#define SELCAP  4096

/* ------------------------- scratch (__device__ globals) ------------------ */
__device__ int      d_leaf_cnt[NLEAF];
__device__ int      d_leaf_off[NLEAF + 1];
__device__ int      d_leaf_cur[NLEAF];
__device__ int      d_perm[MAXN];
__device__ unsigned d_qmask[MAXB][4];
__device__ int      d_qleaf[MAXB][LSEARCH];
__device__ int      d_leaf_q[NLEAF][MAXB];
__device__ int      d_leaf_nq[NLEAF];
__device__ int      d_leaf_sbase[NLEAF];
__device__ int      d_tile_leaf[MAXTILES];
__device__ int      d_tile_lo[MAXTILES];
__device__ int      d_ntiles;
__device__ float    d_lut[MAXB * 1024];
__device__ float    d_sbuf[SCORE_CAP];
__device__ int      d_sel[MAXB * NRE];

__device__ __forceinline__ unsigned fkey(float f) {
    unsigned u = __float_as_uint(f);
    return (u & 0x80000000u) ? ~u : (u | 0x80000000u);
}
__device__ __forceinline__ int clampi(int v, int hi) {   /* [0, hi] */
    return max(0, min(v, hi));
}

/* ---- K1: zero + center scores + top-10 leaves + qmask + PQ LUT ---------- */
__global__ void k_centers(const float* __restrict__ queries,
                          const float* __restrict__ centers,
                          const float* __restrict__ cb) {
    int q = blockIdx.x;
    int tid = threadIdx.x;
    __shared__ float qs[128];
    __shared__ float sc[128];
    __shared__ unsigned smask[4];

    if (q == 0 && tid < NLEAF) { d_leaf_cnt[tid] = 0; d_leaf_cur[tid] = 0; }
    if (tid < 4) smask[tid] = 0u;

    qs[tid] = queries[q * 128 + tid];
    __syncthreads();
    float acc = -FLT_MAX;
    if (tid < NLEAF) {
        acc = 0.f;
        #pragma unroll 8
        for (int d = 0; d < 128; d++) acc += qs[d] * centers[tid * 128 + d];
    }
    sc[tid] = acc;
    __syncthreads();
    if (tid < 32) {
        for (int it = 0; it < LSEARCH; it++) {
            float bv = -FLT_MAX; int bi = 0;
            for (int t = tid; t < NLEAF; t += 32) {
                float v = sc[t];
                if (v > bv || (v == bv && t < bi) || (bv == -FLT_MAX)) {
                    if (v > bv || bv == -FLT_MAX) { bv = v; bi = t; }
                    else if (v == bv && t < bi) bi = t;
                }
            }
            #pragma unroll
            for (int o = 16; o; o >>= 1) {
                float ov = __shfl_xor_sync(0xffffffffu, bv, o);
                int   oi = __shfl_xor_sync(0xffffffffu, bi, o);
                if (ov > bv || (ov == bv && oi < bi)) { bv = ov; bi = oi; }
            }
            if (tid == 0) { d_qleaf[q][it] = bi; sc[bi] = -FLT_MAX; }
            __syncwarp();
        }
    }
    __syncthreads();
    if (tid < LSEARCH) {
        int l = clampi(d_qleaf[q][tid], NLEAF - 1);
        atomicOr(&smask[l >> 5], 1u << (l & 31));
    }
    __syncthreads();
    if (tid < 4) d_qmask[q][tid] = smask[tid];

    /* PQ LUT: d_lut[q*1024 + jj*32 + lane] = LUT[2jj+(lane>=16)][lane&15] */
    #pragma unroll
    for (int r = 0; r < 8; r++) {
        int e = tid + 128 * r;
        int lane = e & 31;
        int j = 2 * (e >> 5) + (lane >= 16 ? 1 : 0);
        int c = lane & 15;
        d_lut[q * 1024 + e] = qs[2 * j]     * cb[(j * 16 + c) * 2 + 0]
                            + qs[2 * j + 1] * cb[(j * 16 + c) * 2 + 1];
    }
}

/* ---- K2: leaf histogram (shared-aggregated) ------------------------------ */
__global__ void k_hist(const int* __restrict__ cl, int N) {
    __shared__ int h[NLEAF];
    int tid = threadIdx.x;
    if (tid < NLEAF) h[tid] = 0;
    __syncthreads();
    for (int n = blockIdx.x * blockDim.x + tid; n < N; n += gridDim.x * blockDim.x)
        atomicAdd(&h[clampi(cl[n], NLEAF - 1)], 1);
    __syncthreads();
    if (tid < NLEAF && h[tid]) atomicAdd(&d_leaf_cnt[tid], h[tid]);
}

/* ---- K3: per-leaf query lists (100 blocks, ballot compaction) ------------ */
__global__ void k_leaflists(int B) {
    int l = blockIdx.x;
    int tid = threadIdx.x, warp = tid >> 5, lane = tid & 31;
    __shared__ int wcnt[4];
    bool mem = (tid < B) && ((d_qmask[tid][l >> 5] >> (l & 31)) & 1u);
    unsigned bal = __ballot_sync(0xffffffffu, mem);
    if (lane == 0) wcnt[warp] = __popc(bal);
    __syncthreads();
    int base = 0;
    for (int w = 0; w < warp; w++) base += wcnt[w];
    if (mem) d_leaf_q[l][clampi(base + __popc(bal & ((1u << lane) - 1u)), MAXB - 1)] = tid;
    if (tid == 0) d_leaf_nq[l] = min(wcnt[0] + wcnt[1] + wcnt[2] + wcnt[3], MAXB);
}

/* ---- K4: parallel prefix sums + tile table ------------------------------- */
__global__ void k_meta() {
    __shared__ int a[128];
    int tid = threadIdx.x;
    int cnt = (tid < NLEAF) ? d_leaf_cnt[tid] : 0;
    int nq  = (tid < NLEAF) ? d_leaf_nq[tid] : 0;

    /* scan 1: leaf offsets */
    a[tid] = cnt; __syncthreads();
    for (int o = 1; o < 128; o <<= 1) {
        int add = (tid >= o) ? a[tid - o] : 0;
        __syncthreads(); a[tid] += add; __syncthreads();
    }
    if (tid < NLEAF) d_leaf_off[tid] = clampi(a[tid] - cnt, MAXN);
    if (tid == NLEAF - 1) d_leaf_off[NLEAF] = clampi(a[tid], MAXN);
    __syncthreads();

    /* scan 2: score-buffer bases (clamped like R1's serial version) */
    long long w = (long long)nq * cnt;
    a[tid] = (int)min(w, (long long)SCORE_CAP); __syncthreads();
    for (int o = 1; o < 128; o <<= 1) {
        int add = (tid >= o) ? a[tid - o] : 0;
        __syncthreads();
        a[tid] = (int)min((long long)a[tid] + add, (long long)SCORE_CAP);
        __syncthreads();
    }
    if (tid < NLEAF) d_leaf_sbase[tid] = clampi(a[tid] - (int)min(w, (long long)SCORE_CAP), SCORE_CAP);
    __syncthreads();

    /* scan 3: tile table */
    int nt = (nq > 0) ? (cnt + TILE - 1) / TILE : 0;
    a[tid] = nt; __syncthreads();
    for (int o = 1; o < 128; o <<= 1) {
        int add = (tid >= o) ? a[tid - o] : 0;
        __syncthreads(); a[tid] += add; __syncthreads();
    }
    int tb = a[tid] - nt;
    if (tid < NLEAF)
        for (int t = 0; t < nt && tb + t < MAXTILES; t++) {
            d_tile_leaf[tb + t] = tid; d_tile_lo[tb + t] = t * TILE;
        }
    if (tid == 127) d_ntiles = min(a[127], MAXTILES);
}

/* ---- K5: scatter (block-aggregated offsets) ------------------------------ */
#define SCHUNK 2048
__global__ void __launch_bounds__(256) k_scatter(const int* __restrict__ cl, int N) {
    __shared__ int lh[NLEAF], lbase[NLEAF], lcur[NLEAF];
    int tid = threadIdx.x;
    int n0 = blockIdx.x * SCHUNK;
    if (tid < NLEAF) { lh[tid] = 0; lcur[tid] = 0; lbase[tid] = 0; }
    __syncthreads();
    int lv[8];
    #pragma unroll
    for (int r = 0; r < 8; r++) {
        int n = n0 + r * 256 + tid;
        lv[r] = (n < N) ? clampi(cl[n], NLEAF - 1) : -1;
        if (lv[r] >= 0) atomicAdd(&lh[lv[r]], 1);
    }
    __syncthreads();
    if (tid < NLEAF && lh[tid]) lbase[tid] = atomicAdd(&d_leaf_cur[tid], lh[tid]);
    __syncthreads();
    #pragma unroll
    for (int r = 0; r < 8; r++) {
        if (lv[r] >= 0) {
            int p = atomicAdd(&lcur[lv[r]], 1);
            int idx = clampi(d_leaf_off[lv[r]] + lbase[lv[r]] + p, MAXN - 1);
            d_perm[idx] = n0 + r * 256 + tid;
        }
    }
}

/* ---- K6: PQ scoring (warp-shuffle LUT) ----------------------------------- */
__global__ void __launch_bounds__(256) k_score(const int* __restrict__ codes) {
    int bx = blockIdx.x;
    if (bx >= d_ntiles) return;
    int leaf = d_tile_leaf[bx];
    int lo   = d_tile_lo[bx];
    int cnt  = d_leaf_cnt[leaf];
    int count = min(TILE, cnt - lo);
    if (count <= 0) return;
    int off  = d_leaf_off[leaf];

    __shared__ unsigned sh[TILE * 9];
    int tid = threadIdx.x;
    for (int i = tid; i < count; i += blockDim.x) {
        int n = d_perm[clampi(off + lo + i, MAXN - 1)];
        const uint4* cp = (const uint4*)(codes + (size_t)n * 64);
        #pragma unroll
        for (int w = 0; w < 8; w++) {
            uint4 a = cp[2 * w], b = cp[2 * w + 1];
            unsigned word = (a.x & 15)        | ((a.y & 15) << 4)
                          | ((a.z & 15) << 8) | ((a.w & 15) << 12)
                          | ((b.x & 15) << 16)| ((b.y & 15) << 20)
                          | ((b.z & 15) << 24)| ((b.w & 15) << 28);
            sh[i * 9 + w] = word;
        }
    }
    __syncthreads();

    int warp = tid >> 5, lane = tid & 31, nw = blockDim.x >> 5;
    int nq = d_leaf_nq[leaf];
    int sbase = d_leaf_sbase[leaf];

    for (int qi = warp; qi < nq; qi += nw) {
        int q = d_leaf_q[leaf][qi];
        float lut[32];
        const float* lp = d_lut + q * 1024 + lane;
        #pragma unroll
        for (int jj = 0; jj < 32; jj++) lut[jj] = lp[jj * 32];

        int wbase = sbase + qi * cnt + lo;
        for (int c0 = 0; c0 < count; c0 += 32) {
            int c  = c0 + lane;
            int cc = min(c, count - 1);
            unsigned cw[8];
            #pragma unroll
            for (int w = 0; w < 8; w++) cw[w] = sh[cc * 9 + w];
            float a0 = 0.f, a1 = 0.f;
            #pragma unroll
            for (int w = 0; w < 8; w++) {
                #pragma unroll
                for (int t = 0; t < 4; t++) {
                    int n0 = (cw[w] >> (8 * t)) & 15;
                    int n1 = (cw[w] >> (8 * t + 4)) & 15;
                    a0 += __shfl_sync(0xffffffffu, lut[4 * w + t], n0);
                    a1 += __shfl_sync(0xffffffffu, lut[4 * w + t], n1 + 16);
                }
            }
            if (c < count) {
                int idx = wbase + c;
                if (idx >= 0 && idx < SCORE_CAP) d_sbuf[idx] = a0 + a1;
            }
        }
    }
}

/* ---- K7: top-100: sampled threshold + pipelined compact + sort ----------- */
__global__ void __launch_bounds__(512) k_select(int B) {
    int q = blockIdx.x;
    if (q >= B) return;
    int tid = threadIdx.x;
    int lane = tid & 31;

    __shared__ unsigned long long keys[SELCAP];
    int* hist = (int*)keys;
    __shared__ int csum[512];
    __shared__ int seg_base[LSEARCH], seg_len[LSEARCH], seg_poff[LSEARCH];
    __shared__ int s_bin, s_cnt, s_tot;

    if (tid < LSEARCH) {
        int l = clampi(d_qleaf[q][tid], NLEAF - 1);
        int nq = d_leaf_nq[l];
        int slot = 0;
        for (int i = 0; i < nq; i++) if (d_leaf_q[l][i] == q) { slot = i; break; }
        seg_base[tid] = clampi(d_leaf_sbase[l] + slot * d_leaf_cnt[l], SCORE_CAP - 1);
        seg_len[tid]  = min(d_leaf_cnt[l], SCORE_CAP - seg_base[tid]);
        seg_poff[tid] = clampi(d_leaf_off[l], MAXN - 1);
    }
    __syncthreads();
    if (tid == 0) {
        int t = 0;
        for (int s = 0; s < LSEARCH; s++) t += seg_len[s];
        s_tot = t;
    }
    __syncthreads();
    int tot = s_tot;

    unsigned T = 0u;
    int attempt = 0;
    int m = 0;

    for (;;) {
        if (tot > SELCAP) {
            for (int i = tid; i < 4096; i += 512) hist[i] = 0;
            if (tid == 0) s_bin = 0;
            __syncthreads();
            int stride = (attempt == 0) ? 16 : 1;
            for (int s = 0; s < LSEARCH; s++) {
                int len = seg_len[s], base = seg_base[s];
                int nel = (len + stride - 1) / stride;
                for (int i = tid; i < nel; i += 512) {
                    unsigned mm = fkey(d_sbuf[base + i * stride]);
                    atomicAdd(&hist[mm >> 20], 1);
                }
            }
            __syncthreads();
            {
                int ssum = 0;
                #pragma unroll
                for (int b = 0; b < 8; b++) ssum += hist[tid * 8 + b];
                csum[tid] = ssum;
            }
            __syncthreads();
            for (int offst = 1; offst < 512; offst <<= 1) {
                int add = (tid + offst < 512) ? csum[tid + offst] : 0;
                __syncthreads();
                csum[tid] += add;
                __syncthreads();
            }
            {
                int running = (tid == 511) ? 0 : csum[tid + 1];
                for (int b = tid * 8 + 7; b >= tid * 8; b--) {
                    int h = hist[b];
                    if (running < NRE && running + h >= NRE) s_bin = b;
                    running += h;
                }
            }
            __syncthreads();
            T = (unsigned)s_bin << 20;
        } else {
            T = 0u;
        }

        /* pipelined compaction with warp-aggregated counter */
        if (tid == 0) s_cnt = 0;
        __syncthreads();
        for (int s = 0; s < LSEARCH; s++) {
            int len = seg_len[s], base = seg_base[s], poff = seg_poff[s];
            int nit = (len + 511) / 512;
            float vcur = (tid < len) ? d_sbuf[base + tid] : -3e38f;
            for (int it = 0; it < nit; it++) {
                int inext = (it + 1) * 512 + tid;
                float vnext = (inext < len) ? d_sbuf[base + inext] : -3e38f;
                int i = it * 512 + tid;
                unsigned mm = fkey(vcur);
                bool pred = (i < len) && (mm >= T);
                unsigned bal = __ballot_sync(0xffffffffu, pred);
                if (bal) {
                    int basep = 0;
                    if (lane == 0) basep = atomicAdd(&s_cnt, __popc(bal));
                    basep = __shfl_sync(0xffffffffu, basep, 0);
                    if (pred) {
                        int pos = basep + __popc(bal & ((1u << lane) - 1u));
                        if (pos < SELCAP) {
                            int id = d_perm[clampi(poff + i, MAXN - 1)];
                            keys[pos] = ((unsigned long long)mm << 32)
                                      | (unsigned)(~(unsigned)id);
                        }
                    }
                }
                vcur = vnext;
            }
        }
        __syncthreads();
        m = s_cnt;
        if (m <= SELCAP || attempt >= 1 || tot <= SELCAP) break;
        attempt = 1;
        __syncthreads();
    }

    int m_eff = min(m, SELCAP);
    int NS = 128;
    while (NS < m_eff) NS <<= 1;
    for (int i = tid; i < NS; i += 512)
        if (i >= m_eff) keys[i] = 0ull;
    __syncthreads();

    for (int k2 = 2; k2 <= NS; k2 <<= 1) {
        for (int j = k2 >> 1; j > 0; j >>= 1) {
            for (int idx = tid; idx < (NS >> 1); idx += 512) {
                int i = ((idx / j) * (j << 1)) + (idx % j);
                int p = i + j;
                bool dsc = ((i & k2) == 0);
                unsigned long long a = keys[i], b = keys[p];
                if ((a < b) == dsc) { keys[i] = b; keys[p] = a; }
            }
            __syncthreads();
        }
    }

    for (int r = tid; r < NRE; r += 512) {
        unsigned long long kk = (r < m_eff) ? keys[r] : 0ull;
        d_sel[q * NRE + r] = (kk == 0ull) ? -1
                           : (int)(~(unsigned)(kk & 0xffffffffull));
    }
}

/* ---- K8: exact rerank + final top-k -------------------------------------- */
__global__ void __launch_bounds__(256) k_rerank(const float* __restrict__ queries,
                         const float* __restrict__ cands,
                         const int*   __restrict__ identifiers,
                         float* __restrict__ out,
                         int B, int N, int kk) {
    int q = blockIdx.x;
    if (q >= B) return;
    int tid = threadIdx.x, warp = tid >> 5, lane = tid & 31;
    __shared__ float qs[128];
    __shared__ float ex[NRE];
    __shared__ int sel[NRE];
    if (tid < 128) qs[tid] = queries[q * 128 + tid];
    if (tid < NRE) sel[tid] = d_sel[q * NRE + tid];
    __syncthreads();

    for (int r = warp; r < NRE; r += 8) {
        int id = sel[r];
        float acc = 0.f;
        bool ok = ((unsigned)id < (unsigned)N);
        if (ok) {
            const float* c = cands + (size_t)id * 128;
            acc = qs[lane] * c[lane] + qs[lane + 32] * c[lane + 32]
                + qs[lane + 64] * c[lane + 64] + qs[lane + 96] * c[lane + 96];
        }
        #pragma unroll
        for (int o = 16; o; o >>= 1) acc += __shfl_xor_sync(0xffffffffu, acc, o);
        if (lane == 0) ex[r] = ok ? acc : -1e30f;
    }
    __syncthreads();

    if (warp == 0) {
        for (int it = 0; it < kk; it++) {
            float bv = -FLT_MAX; int bi = NRE;
            for (int r = lane; r < NRE; r += 32) {
                float v = ex[r];
                if (v > bv || (v == bv && r < bi)) { bv = v; bi = r; }
            }
            #pragma unroll
            for (int o = 16; o; o >>= 1) {
                float ov = __shfl_xor_sync(0xffffffffu, bv, o);
                int   oi = __shfl_xor_sync(0xffffffffu, bi, o);
                if (ov > bv || (ov == bv && oi < bi)) { bv = ov; bi = oi; }
            }
            if (lane == 0) {
                int cid = (bi < NRE) ? sel[bi] : -1;
                out[q * kk + it] = bv;
                float idv = 0.f;
                if ((unsigned)cid < (unsigned)N) idv = (float)identifiers[cid];
                out[(size_t)B * kk + q * kk + it] = idv;
                if (bi < NRE) ex[bi] = -FLT_MAX;
            }
            __syncwarp();
        }
    }
}

/* ---- host launcher ------------------------------------------------------- */
extern "C" void kernel_launch(void* const* d_in, const int* in_sizes, int n_in,
                              void* d_out, int out_size) {
    const float* queries    = (const float*)d_in[0];
    const float* candidates = (const float*)d_in[1];
    const float* centers    = (const float*)d_in[2];
    const float* codebooks  = (const float*)d_in[3];
    const int*   codes      = (const int*)d_in[4];
    const int*   cand_leaf  = (const int*)d_in[5];
    const int*   identifiers= (const int*)d_in[6];

    int B = in_sizes[0] / 128;
    int N = in_sizes[1] / 128;
    if (B < 1) B = 1;
    if (B > MAXB) B = MAXB;
    if (N < 1) N = 1;
    if (N > MAXN) N = MAXN;          /* hard cap: all scratch sized for MAXN */
    int kk = (B > 0) ? out_size / (2 * B) : 10;
    if (kk <= 0 || kk > NRE) kk = 10;

    float* out = (float*)d_out;

    k_centers<<<B, 128>>>(queries, centers, codebooks);
    k_hist<<<256, 256>>>(cand_leaf, N);
    k_leaflists<<<NLEAF, 128>>>(B);
    k_meta<<<1, 128>>>();
    k_scatter<<<(N + SCHUNK - 1) / SCHUNK, 256>>>(cand_leaf, N);

    int maxTiles = (N + TILE - 1) / TILE + NLEAF;
    if (maxTiles > MAXTILES) maxTiles = MAXTILES;
    k_score<<<maxTiles, 256>>>(codes);

    k_select<<<B, 512>>>(B);
    k_rerank<<<B, 256>>>(queries, candidates, identifiers, out, B, N, kk);
}